// round 1
// baseline (speedup 1.0000x reference)
#include <cuda_runtime.h>
#include <math.h>

#define B 64
#define T 256
#define D 512
#define G4 2048
#define M_ROWS (B * T)   // 16384
#define DIN2 1024

// ---------------- device scratch (static; no allocation APIs) ----------------
__device__ float g_xz_f[(size_t)M_ROWS * G4];   // input projection, fwd dir (reused by both layers)
__device__ float g_xz_b[(size_t)M_ROWS * G4];   // input projection, bwd dir
__device__ float g_y1[(size_t)M_ROWS * DIN2];   // layer-1 output [B*T, 1024]
__device__ float g_h[2][2 * B * D];             // [pingpong][dir*B*D]
__device__ float g_c[2 * B * D];                // [dir*B*D]
__device__ unsigned char g_mask[M_ROWS];

// ---------------- mask: any(X[b,t,:] != 0) ----------------
__global__ void mask_kernel(const float* __restrict__ X) {
    int row = blockIdx.x * 4 + (threadIdx.x >> 5);
    if (row >= M_ROWS) return;
    int lane = threadIdx.x & 31;
    const float* p = X + (size_t)row * D;
    int any = 0;
    for (int k = lane; k < D; k += 32) any |= (p[k] != 0.0f);
    any = __any_sync(0xffffffffu, any);
    if (lane == 0) g_mask[row] = (unsigned char)any;
}

// ---------------- C[M,2048] = A[M,K] @ W[K,2048] + bias ----------------
// BM=64, BN=64, BK=16, 256 threads, 4x4 register tile.
__global__ void __launch_bounds__(256) gemm_bias_kernel(
    const float* __restrict__ Aext, int a_is_y1,
    const float* __restrict__ W, const float* __restrict__ bias,
    int c_sel, int K)
{
    const float* A = a_is_y1 ? g_y1 : Aext;
    float* C = c_sel ? g_xz_b : g_xz_f;

    __shared__ float As[16][64];   // [k][m]
    __shared__ float Ws[16][64];   // [k][n]

    int tid = threadIdx.x;
    int m0 = blockIdx.y * 64, n0 = blockIdx.x * 64;
    int lm = tid >> 2, lk = (tid & 3) << 2;
    int wk = tid >> 4, wn = (tid & 15) << 2;
    int mi = (tid >> 4) << 2, ni = (tid & 15) << 2;

    float acc[4][4];
#pragma unroll
    for (int r = 0; r < 4; r++)
#pragma unroll
        for (int s = 0; s < 4; s++) acc[r][s] = 0.0f;

    for (int k0 = 0; k0 < K; k0 += 16) {
        float4 a4 = *(const float4*)&A[(size_t)(m0 + lm) * K + k0 + lk];
        As[lk + 0][lm] = a4.x; As[lk + 1][lm] = a4.y;
        As[lk + 2][lm] = a4.z; As[lk + 3][lm] = a4.w;
        *(float4*)&Ws[wk][wn] = *(const float4*)&W[(size_t)(k0 + wk) * G4 + n0 + wn];
        __syncthreads();
#pragma unroll
        for (int kk = 0; kk < 16; kk++) {
            float4 av = *(float4*)&As[kk][mi];
            float4 wv = *(float4*)&Ws[kk][ni];
            float a[4] = {av.x, av.y, av.z, av.w};
            float w[4] = {wv.x, wv.y, wv.z, wv.w};
#pragma unroll
            for (int r = 0; r < 4; r++)
#pragma unroll
                for (int s = 0; s < 4; s++) acc[r][s] += a[r] * w[s];
        }
        __syncthreads();
    }
#pragma unroll
    for (int r = 0; r < 4; r++) {
        size_t crow = (size_t)(m0 + mi + r) * G4 + n0 + ni;
#pragma unroll
        for (int s = 0; s < 4; s++) C[crow + s] = acc[r][s] + bias[n0 + ni + s];
    }
}

// ---------------- zero h (both pings) and c ----------------
__global__ void zero_state_kernel() {
    int i = blockIdx.x * blockDim.x + threadIdx.x;
    if (i < 2 * 2 * B * D) ((float*)g_h)[i] = 0.0f;
    if (i < 2 * B * D) g_c[i] = 0.0f;
}

// ---------------- one LSTM timestep, both directions ----------------
// 128 CTAs: dir = blk>>6, 8 hidden units each (32 gate columns).
// smem: h_s[64][516] staged h (132KB), u_s[32][516] staged U cols (66KB).
#define SMEM_STEP ((64 * 516 + 32 * 516) * 4)

__global__ void __launch_bounds__(128) lstm_step_kernel(
    const float* __restrict__ Uf, const float* __restrict__ Ub,
    float* dout, int out_is_y1, int out_stride,
    int ping, int t_f, int t_b, int first)
{
    extern __shared__ float sm[];
    float* h_s = sm;                 // 64*516
    float* u_s = sm + 64 * 516;      // 32*516

    int tid = threadIdx.x;
    int dir = blockIdx.x >> 6;
    int u0 = (blockIdx.x & 63) << 3;

    const float* U = dir ? Ub : Uf;
    const float* xz = dir ? g_xz_b : g_xz_f;
    const float* h_in = g_h[ping] + dir * (B * D);
    float* h_out = g_h[ping ^ 1] + dir * (B * D);
    float* c_st = g_c + dir * (B * D);
    float* outb = (out_is_y1 ? g_y1 : dout) + dir * D;   // column offset 0 / 512
    int t_d = dir ? t_b : t_f;
    int t_prev = dir ? t_b + 1 : t_f - 1;

    // stage h [64,512] into smem (padded rows of 516)
    for (int i = tid; i < 64 * 128; i += 128) {
        int b = i >> 7, k4 = (i & 127) << 2;
        *(float4*)&h_s[b * 516 + k4] = *(const float4*)&h_in[b * 512 + k4];
    }
    // stage this CTA's 32 U columns, transposed to [col][k]
    for (int i = tid; i < 32 * 512; i += 128) {
        int k = i >> 5, j = i & 31;
        int col = ((j >> 3) << 9) + u0 + (j & 7);
        u_s[j * 516 + k] = U[(size_t)k * G4 + col];
    }
    __syncthreads();

    // z[64][32] = h @ U_slice ; thread tile 4x4
    int b0 = (tid >> 3) << 2, c0 = (tid & 7) << 2;
    float acc[4][4];
#pragma unroll
    for (int r = 0; r < 4; r++)
#pragma unroll
        for (int s = 0; s < 4; s++) acc[r][s] = 0.0f;

#pragma unroll 4
    for (int k = 0; k < 512; k += 4) {
        float4 hv[4], uv[4];
#pragma unroll
        for (int r = 0; r < 4; r++) hv[r] = *(const float4*)&h_s[(b0 + r) * 516 + k];
#pragma unroll
        for (int s = 0; s < 4; s++) uv[s] = *(const float4*)&u_s[(c0 + s) * 516 + k];
#pragma unroll
        for (int r = 0; r < 4; r++)
#pragma unroll
            for (int s = 0; s < 4; s++)
                acc[r][s] += hv[r].x * uv[s].x + hv[r].y * uv[s].y +
                             hv[r].z * uv[s].z + hv[r].w * uv[s].w;
    }
    __syncthreads();

    // park z in smem (reuse h_s region) for cross-thread gate combine
    float* z_s = sm;   // [64][33]
#pragma unroll
    for (int r = 0; r < 4; r++)
#pragma unroll
        for (int s = 0; s < 4; s++) z_s[(b0 + r) * 33 + (c0 + s)] = acc[r][s];
    __syncthreads();

    // gates + state update + masked emit; 512 (b,unit) elements
    for (int e = tid; e < 512; e += 128) {
        int b = e >> 3, u = e & 7;
        int row = b * T + t_d;
        int cb = u0 + u;
        size_t xr = (size_t)row * G4;
        float zi = z_s[b * 33 + u]      + xz[xr + cb];
        float zf = z_s[b * 33 + 8 + u]  + xz[xr + 512 + cb];
        float zg = z_s[b * 33 + 16 + u] + xz[xr + 1024 + cb];
        float zo = z_s[b * 33 + 24 + u] + xz[xr + 1536 + cb];
        float iv = 1.0f / (1.0f + expf(-zi));
        float fv = 1.0f / (1.0f + expf(-zf));
        float gv = tanhf(zg);
        float ov = 1.0f / (1.0f + expf(-zo));
        int sidx = b * D + cb;
        float c_old = c_st[sidx];
        float c_new = fv * c_old + iv * gv;
        float h_new = ov * tanhf(c_new);
        bool m = g_mask[row] != 0;
        c_st[sidx] = m ? c_new : c_old;
        h_out[sidx] = m ? h_new : h_in[sidx];
        float prev = first ? 0.0f : outb[(size_t)(b * T + t_prev) * out_stride + cb];
        outb[(size_t)row * out_stride + cb] = m ? h_new : prev;
    }
}

// ---------------- final hidden/cell concat into d_out tail ----------------
__global__ void finalize_kernel(float* dout, int out_size) {
    int i = blockIdx.x * blockDim.x + threadIdx.x;
    if (i >= B * 2 * D) return;
    size_t hoff = (size_t)B * T * 1024;
    if ((size_t)out_size < hoff + 2 * (size_t)(B * 2 * D)) return;  // no state outputs expected
    int b = i >> 10, j = i & 1023;
    int dir = j >> 9, u = j & 511;
    int sidx = dir * (B * D) + b * D + u;
    dout[hoff + i] = g_h[0][sidx];                  // 256 steps => final ping = 0
    dout[hoff + B * 2 * D + i] = g_c[sidx];
}

// ---------------- host orchestration (graph-capturable) ----------------
extern "C" void kernel_launch(void* const* d_in, const int* in_sizes, int n_in,
                              void* d_out, int out_size) {
    const float* X   = (const float*)d_in[0];
    const float* Wf1 = (const float*)d_in[1];
    const float* Uf1 = (const float*)d_in[2];
    const float* bf1 = (const float*)d_in[3];
    const float* Wb1 = (const float*)d_in[4];
    const float* Ub1 = (const float*)d_in[5];
    const float* bb1 = (const float*)d_in[6];
    const float* Wf2 = (const float*)d_in[7];
    const float* Uf2 = (const float*)d_in[8];
    const float* bf2 = (const float*)d_in[9];
    const float* Wb2 = (const float*)d_in[10];
    const float* Ub2 = (const float*)d_in[11];
    const float* bb2 = (const float*)d_in[12];
    float* out = (float*)d_out;

    cudaFuncSetAttribute(lstm_step_kernel,
                         cudaFuncAttributeMaxDynamicSharedMemorySize, SMEM_STEP);

    mask_kernel<<<M_ROWS / 4, 128>>>(X);

    dim3 ggrid(G4 / 64, M_ROWS / 64);

    // ---- layer 1 ----
    gemm_bias_kernel<<<ggrid, 256>>>(X, 0, Wf1, bf1, 0, 512);
    gemm_bias_kernel<<<ggrid, 256>>>(X, 0, Wb1, bb1, 1, 512);
    zero_state_kernel<<<512, 256>>>();
    for (int s = 0; s < T; s++)
        lstm_step_kernel<<<128, 128, SMEM_STEP>>>(Uf1, Ub1, out, 1, 1024,
                                                  s & 1, s, T - 1 - s, s == 0);

    // ---- layer 2 ----
    gemm_bias_kernel<<<ggrid, 256>>>(nullptr, 1, Wf2, bf2, 0, 1024);
    gemm_bias_kernel<<<ggrid, 256>>>(nullptr, 1, Wb2, bb2, 1, 1024);
    zero_state_kernel<<<512, 256>>>();
    for (int s = 0; s < T; s++)
        lstm_step_kernel<<<128, 128, SMEM_STEP>>>(Uf2, Ub2, out, 0, 1024,
                                                  s & 1, s, T - 1 - s, s == 0);

    finalize_kernel<<<256, 256>>>(out, out_size);
}

// round 2
// speedup vs baseline: 1.5483x; 1.5483x over previous
#include <cuda_runtime.h>
#include <math.h>

#define B 64
#define T 256
#define D 512
#define G4 2048
#define M_ROWS (B * T)   // 16384
#define DIN2 1024

typedef unsigned long long ull;

// ---------------- f32x2 helpers ----------------
__device__ __forceinline__ void fma2(ull &d, ull a, ull b) {
    asm("fma.rn.f32x2 %0, %1, %2, %0;" : "+l"(d) : "l"(a), "l"(b));
}
__device__ __forceinline__ ull dup2(float v) {
    ull r; unsigned u = __float_as_uint(v);
    asm("mov.b64 %0, {%1, %1};" : "=l"(r) : "r"(u));
    return r;
}
__device__ __forceinline__ float2 unpk(ull v) {
    float2 f;
    asm("mov.b64 {%0, %1}, %2;" : "=f"(f.x), "=f"(f.y) : "l"(v));
    return f;
}

// ---------------- device scratch ----------------
__device__ float g_xz_f[(size_t)M_ROWS * G4];
__device__ float g_xz_b[(size_t)M_ROWS * G4];
__device__ float g_y1[(size_t)M_ROWS * DIN2];
__device__ float g_h[2][2 * B * D];
__device__ float g_c[2 * B * D];
__device__ unsigned char g_mask[M_ROWS];

// ---------------- mask ----------------
__global__ void mask_kernel(const float* __restrict__ X) {
    int row = blockIdx.x * 4 + (threadIdx.x >> 5);
    if (row >= M_ROWS) return;
    int lane = threadIdx.x & 31;
    const float* p = X + (size_t)row * D;
    int any = 0;
    for (int k = lane; k < D; k += 32) any |= (p[k] != 0.0f);
    any = __any_sync(0xffffffffu, any);
    if (lane == 0) g_mask[row] = (unsigned char)any;
}

// ---------------- GEMM: C[M,2048] = A[M,K] @ W[K,2048] + bias ----------------
// BM=BN=128, BK=16, 256 threads, 8x8/thread via f32x2, double-buffered.
__global__ void __launch_bounds__(256, 2) gemm_bias_kernel(
    const float* __restrict__ Aext, int a_is_y1,
    const float* __restrict__ W, const float* __restrict__ bias,
    int c_sel, int K)
{
    const float* A = a_is_y1 ? g_y1 : Aext;
    float* C = c_sel ? g_xz_b : g_xz_f;

    __shared__ float As[2][16 * 128];
    __shared__ float Bs[2][16 * 128];

    int tid = threadIdx.x;
    int m0 = blockIdx.y << 7, n0 = blockIdx.x << 7;
    int warp = tid >> 5, lane = tid & 31;
    int wm = (warp & 3) << 5, wn = (warp >> 2) << 6;
    int lm = (lane >> 3) << 2, ln = (lane & 7) << 2;
    int am = tid & 127, akg = tid >> 7;        // A: (am, akg) and (am, akg+2)
    int bn4 = tid & 31, bk0 = tid >> 5;        // B: (bk0, bn4) and (bk0+8, bn4)

    ull acc[8][4];
#pragma unroll
    for (int r = 0; r < 8; r++)
#pragma unroll
        for (int s = 0; s < 4; s++) acc[r][s] = 0ULL;

    float4 aR[2], bR[2];
    const size_t arow = (size_t)(m0 + am) * K;

#define LDG_TILE(k0)                                                          \
    aR[0] = *(const float4*)&A[arow + (k0) + (akg << 2)];                     \
    aR[1] = *(const float4*)&A[arow + (k0) + ((akg + 2) << 2)];               \
    bR[0] = *(const float4*)&W[(size_t)((k0) + bk0) * G4 + n0 + (bn4 << 2)];  \
    bR[1] = *(const float4*)&W[(size_t)((k0) + bk0 + 8) * G4 + n0 + (bn4 << 2)];

#define STS_TILE(buf)                                                         \
    {                                                                         \
        float* Ad = As[buf]; float* Bd = Bs[buf];                             \
        Ad[((akg << 2) + 0) * 128 + am] = aR[0].x;                            \
        Ad[((akg << 2) + 1) * 128 + am] = aR[0].y;                            \
        Ad[((akg << 2) + 2) * 128 + am] = aR[0].z;                            \
        Ad[((akg << 2) + 3) * 128 + am] = aR[0].w;                            \
        Ad[(((akg + 2) << 2) + 0) * 128 + am] = aR[1].x;                      \
        Ad[(((akg + 2) << 2) + 1) * 128 + am] = aR[1].y;                      \
        Ad[(((akg + 2) << 2) + 2) * 128 + am] = aR[1].z;                      \
        Ad[(((akg + 2) << 2) + 3) * 128 + am] = aR[1].w;                      \
        *(float4*)&Bd[bk0 * 128 + (bn4 << 2)] = bR[0];                        \
        *(float4*)&Bd[(bk0 + 8) * 128 + (bn4 << 2)] = bR[1];                  \
    }

    LDG_TILE(0);
    STS_TILE(0);
    __syncthreads();

    int KT = K >> 4;
    for (int kt = 0; kt < KT; kt++) {
        int cur = kt & 1;
        if (kt + 1 < KT) { LDG_TILE((kt + 1) << 4); }
        const float* Ab = As[cur];
        const float* Bb = Bs[cur];
#pragma unroll
        for (int kk = 0; kk < 16; kk++) {
            float4 a0 = *(const float4*)&Ab[kk * 128 + wm + lm];
            float4 a1 = *(const float4*)&Ab[kk * 128 + wm + lm + 16];
            ulonglong2 b0 = *(const ulonglong2*)&Bb[kk * 128 + wn + ln];
            ulonglong2 b1 = *(const ulonglong2*)&Bb[kk * 128 + wn + ln + 32];
            ull ap[8];
            ap[0] = dup2(a0.x); ap[1] = dup2(a0.y); ap[2] = dup2(a0.z); ap[3] = dup2(a0.w);
            ap[4] = dup2(a1.x); ap[5] = dup2(a1.y); ap[6] = dup2(a1.z); ap[7] = dup2(a1.w);
#pragma unroll
            for (int r = 0; r < 8; r++) {
                fma2(acc[r][0], ap[r], b0.x);
                fma2(acc[r][1], ap[r], b0.y);
                fma2(acc[r][2], ap[r], b1.x);
                fma2(acc[r][3], ap[r], b1.y);
            }
        }
        if (kt + 1 < KT) {
            STS_TILE(cur ^ 1);
            __syncthreads();
        }
    }

    float4 bias0 = *(const float4*)&bias[n0 + wn + ln];
    float4 bias1 = *(const float4*)&bias[n0 + wn + ln + 32];
#pragma unroll
    for (int r = 0; r < 8; r++) {
        int mrow = m0 + wm + lm + (r < 4 ? r : 12 + r);
        float2 p0 = unpk(acc[r][0]), p1 = unpk(acc[r][1]);
        float2 p2 = unpk(acc[r][2]), p3 = unpk(acc[r][3]);
        float4 v0 = {p0.x + bias0.x, p0.y + bias0.y, p1.x + bias0.z, p1.y + bias0.w};
        float4 v1 = {p2.x + bias1.x, p2.y + bias1.y, p3.x + bias1.z, p3.y + bias1.w};
        size_t crow = (size_t)mrow * G4 + n0 + wn + ln;
        *(float4*)&C[crow] = v0;
        *(float4*)&C[crow + 32] = v1;
    }
#undef LDG_TILE
#undef STS_TILE
}

// ---------------- zero state ----------------
__global__ void zero_state_kernel() {
    int i = blockIdx.x * blockDim.x + threadIdx.x;
    if (i < 2 * 2 * B * D) ((float*)g_h)[i] = 0.0f;
    if (i < 2 * B * D) g_c[i] = 0.0f;
}

// ---------------- one LSTM timestep, both directions ----------------
// 128 CTAs (dir = blk>>6, 8 hidden units = 32 gate cols each), 128 threads.
// smem: h_s[64][512] swizzled (128KB) + u_s[32][512] swizzled (64KB) = 192KB.
// Compute: 2 k-groups x 64 threads, 8(b) x 4(col) per thread, f32x2 FMAs.
#define SMEM_STEP ((64 * 512 + 32 * 512) * 4)

__global__ void __launch_bounds__(128) lstm_step_kernel(
    const float* __restrict__ Uf, const float* __restrict__ Ub,
    float* dout, int out_is_y1, int out_stride,
    int ping, int t_f, int t_b, int first)
{
    extern __shared__ float sm[];
    float* h_s = sm;               // 64 rows * 512, chunk-swizzled by (b>>3)
    float* u_s = sm + 64 * 512;    // 32 rows * 512, chunk-swizzled by (j>>2)

    int tid = threadIdx.x;
    int dir = blockIdx.x >> 6;
    int u0 = (blockIdx.x & 63) << 3;

    const float* U = dir ? Ub : Uf;
    const float* xz = dir ? g_xz_b : g_xz_f;
    const float* h_in = g_h[ping] + dir * (B * D);
    float* h_out = g_h[ping ^ 1] + dir * (B * D);
    float* c_st = g_c + dir * (B * D);
    float* outb = (out_is_y1 ? g_y1 : dout) + dir * D;
    int t_d = dir ? t_b : t_f;
    int t_prev = dir ? t_b + 1 : t_f - 1;

    // ---- stage h [64,512]: conflict-free LDG.128 -> swizzled STS.128 ----
    for (int i = tid; i < 64 * 128; i += 128) {
        int b = i >> 7, c = i & 127;
        float4 v = *(const float4*)&h_in[(b << 9) + (c << 2)];
        *(float4*)&h_s[(b << 9) + (((c ^ ((b >> 3) & 7)) << 2))] = v;
    }
    // ---- stage U slice (32 cols x 512 k): coalesced float4 LDG, swizzled STS ----
    for (int i = tid; i < 4096; i += 128) {
        int k = i >> 3, q = i & 7;
        int g = q >> 1, half = q & 1;
        int col = (g << 9) + u0 + (half << 2);
        float4 v = *(const float4*)&U[(size_t)k * G4 + col];
        int jb = (g << 3) + (half << 2);
        int chunk = k >> 2, klo = k & 3;
        const float* vp = (const float*)&v;
#pragma unroll
        for (int comp = 0; comp < 4; comp++) {
            int j = jb + comp;
            u_s[(j << 9) + (((chunk ^ ((j >> 2) & 7)) << 2) | klo)] = vp[comp];
        }
    }
    __syncthreads();

    // ---- z[64][32] = h @ U_slice, split k over 2 groups ----
    int t = tid & 63, kg = tid >> 6;
    int tb = t >> 3, tc = t & 7;
    int b0 = tb << 3, c0 = tc << 2;

    ull acc[8][4];
#pragma unroll
    for (int r = 0; r < 8; r++)
#pragma unroll
        for (int s = 0; s < 4; s++) acc[r][s] = 0ULL;

    int cbeg = kg << 6;
    const float* hbase = h_s + (b0 << 9);
    const float* ubase = u_s + (c0 << 9);
#pragma unroll 2
    for (int ci = 0; ci < 64; ci++) {
        int c = cbeg + ci;
        int ph = (c ^ tb) << 2;
        int pu = (c ^ tc) << 2;
        ulonglong2 hv[8], uv[4];
#pragma unroll
        for (int r = 0; r < 8; r++) hv[r] = *(const ulonglong2*)&hbase[(r << 9) + ph];
#pragma unroll
        for (int s = 0; s < 4; s++) uv[s] = *(const ulonglong2*)&ubase[(s << 9) + pu];
#pragma unroll
        for (int r = 0; r < 8; r++)
#pragma unroll
            for (int s = 0; s < 4; s++) {
                fma2(acc[r][s], hv[r].x, uv[s].x);
                fma2(acc[r][s], hv[r].y, uv[s].y);
            }
    }
    __syncthreads();

    // ---- combine partials into z_s[64][33] (reuses smem) ----
    float* z_s = sm;
    if (kg == 0) {
#pragma unroll
        for (int r = 0; r < 8; r++)
#pragma unroll
            for (int s = 0; s < 4; s++) {
                float2 f = unpk(acc[r][s]);
                z_s[(b0 + r) * 33 + c0 + s] = f.x + f.y;
            }
    }
    __syncthreads();
    if (kg == 1) {
#pragma unroll
        for (int r = 0; r < 8; r++)
#pragma unroll
            for (int s = 0; s < 4; s++) {
                float2 f = unpk(acc[r][s]);
                z_s[(b0 + r) * 33 + c0 + s] += f.x + f.y;
            }
    }
    __syncthreads();

    // ---- gates + state update + masked emit ----
    for (int e = tid; e < 512; e += 128) {
        int b = e >> 3, u = e & 7;
        int row = b * T + t_d;
        int cb = u0 + u;
        size_t xr = (size_t)row * G4;
        float zi = z_s[b * 33 + u]      + xz[xr + cb];
        float zf = z_s[b * 33 + 8 + u]  + xz[xr + 512 + cb];
        float zg = z_s[b * 33 + 16 + u] + xz[xr + 1024 + cb];
        float zo = z_s[b * 33 + 24 + u] + xz[xr + 1536 + cb];
        float iv = 1.0f / (1.0f + expf(-zi));
        float fv = 1.0f / (1.0f + expf(-zf));
        float gv = tanhf(zg);
        float ov = 1.0f / (1.0f + expf(-zo));
        int sidx = b * D + cb;
        float c_old = c_st[sidx];
        float c_new = fv * c_old + iv * gv;
        float h_new = ov * tanhf(c_new);
        bool m = g_mask[row] != 0;
        c_st[sidx] = m ? c_new : c_old;
        h_out[sidx] = m ? h_new : h_in[sidx];
        float prev = first ? 0.0f : outb[(size_t)(b * T + t_prev) * out_stride + cb];
        outb[(size_t)row * out_stride + cb] = m ? h_new : prev;
    }
}

// ---------------- final hidden/cell concat ----------------
__global__ void finalize_kernel(float* dout, int out_size) {
    int i = blockIdx.x * blockDim.x + threadIdx.x;
    if (i >= B * 2 * D) return;
    size_t hoff = (size_t)B * T * 1024;
    if ((size_t)out_size < hoff + 2 * (size_t)(B * 2 * D)) return;
    int b = i >> 10, j = i & 1023;
    int dir = j >> 9, u = j & 511;
    int sidx = dir * (B * D) + b * D + u;
    dout[hoff + i] = g_h[0][sidx];
    dout[hoff + B * 2 * D + i] = g_c[sidx];
}

// ---------------- host orchestration ----------------
extern "C" void kernel_launch(void* const* d_in, const int* in_sizes, int n_in,
                              void* d_out, int out_size) {
    const float* X   = (const float*)d_in[0];
    const float* Wf1 = (const float*)d_in[1];
    const float* Uf1 = (const float*)d_in[2];
    const float* bf1 = (const float*)d_in[3];
    const float* Wb1 = (const float*)d_in[4];
    const float* Ub1 = (const float*)d_in[5];
    const float* bb1 = (const float*)d_in[6];
    const float* Wf2 = (const float*)d_in[7];
    const float* Uf2 = (const float*)d_in[8];
    const float* bf2 = (const float*)d_in[9];
    const float* Wb2 = (const float*)d_in[10];
    const float* Ub2 = (const float*)d_in[11];
    const float* bb2 = (const float*)d_in[12];
    float* out = (float*)d_out;

    cudaFuncSetAttribute(lstm_step_kernel,
                         cudaFuncAttributeMaxDynamicSharedMemorySize, SMEM_STEP);

    mask_kernel<<<M_ROWS / 4, 128>>>(X);

    dim3 ggrid(G4 / 128, M_ROWS / 128);

    // ---- layer 1 ----
    gemm_bias_kernel<<<ggrid, 256>>>(X, 0, Wf1, bf1, 0, 512);
    gemm_bias_kernel<<<ggrid, 256>>>(X, 0, Wb1, bb1, 1, 512);
    zero_state_kernel<<<512, 256>>>();
    for (int s = 0; s < T; s++)
        lstm_step_kernel<<<128, 128, SMEM_STEP>>>(Uf1, Ub1, out, 1, 1024,
                                                  s & 1, s, T - 1 - s, s == 0);

    // ---- layer 2 ----
    gemm_bias_kernel<<<ggrid, 256>>>(nullptr, 1, Wf2, bf2, 0, 1024);
    gemm_bias_kernel<<<ggrid, 256>>>(nullptr, 1, Wb2, bb2, 1, 1024);
    zero_state_kernel<<<512, 256>>>();
    for (int s = 0; s < T; s++)
        lstm_step_kernel<<<128, 128, SMEM_STEP>>>(Uf2, Ub2, out, 0, 1024,
                                                  s & 1, s, T - 1 - s, s == 0);

    finalize_kernel<<<256, 256>>>(out, out_size);
}

// round 3
// speedup vs baseline: 2.0985x; 1.3554x over previous
#include <cuda_runtime.h>
#include <math.h>

#define B 64
#define T 256
#define D 512
#define G4 2048
#define M_ROWS (B * T)   // 16384
#define DIN2 1024

typedef unsigned long long ull;

// ---------------- f32x2 helpers ----------------
__device__ __forceinline__ void fma2(ull &d, ull a, ull b) {
    asm("fma.rn.f32x2 %0, %1, %2, %0;" : "+l"(d) : "l"(a), "l"(b));
}
__device__ __forceinline__ ull dup2(float v) {
    ull r; unsigned u = __float_as_uint(v);
    asm("mov.b64 %0, {%1, %1};" : "=l"(r) : "r"(u));
    return r;
}
__device__ __forceinline__ float2 unpk(ull v) {
    float2 f;
    asm("mov.b64 {%0, %1}, %2;" : "=f"(f.x), "=f"(f.y) : "l"(v));
    return f;
}

// ---------------- device scratch ----------------
__device__ float g_xz_f[(size_t)M_ROWS * G4];
__device__ float g_xz_b[(size_t)M_ROWS * G4];
__device__ float g_y1[(size_t)M_ROWS * DIN2];
__device__ float g_h[2][2 * B * D];
__device__ float g_c[2 * B * D];
__device__ unsigned char g_mask[M_ROWS];
__device__ unsigned g_bcount[2];
__device__ volatile unsigned g_bgen[2];

// ---------------- mask ----------------
__global__ void mask_kernel(const float* __restrict__ X) {
    int row = blockIdx.x * 4 + (threadIdx.x >> 5);
    if (row >= M_ROWS) return;
    int lane = threadIdx.x & 31;
    const float* p = X + (size_t)row * D;
    int any = 0;
    for (int k = lane; k < D; k += 32) any |= (p[k] != 0.0f);
    any = __any_sync(0xffffffffu, any);
    if (lane == 0) g_mask[row] = (unsigned char)any;
}

// ---------------- GEMM: C[M,2048] = A[M,K] @ W[K,2048] + bias ----------------
__global__ void __launch_bounds__(256, 2) gemm_bias_kernel(
    const float* __restrict__ Aext, int a_is_y1,
    const float* __restrict__ W, const float* __restrict__ bias,
    int c_sel, int K)
{
    const float* A = a_is_y1 ? g_y1 : Aext;
    float* C = c_sel ? g_xz_b : g_xz_f;

    __shared__ float As[2][16 * 128];
    __shared__ float Bs[2][16 * 128];

    int tid = threadIdx.x;
    int m0 = blockIdx.y << 7, n0 = blockIdx.x << 7;
    int warp = tid >> 5, lane = tid & 31;
    int wm = (warp & 3) << 5, wn = (warp >> 2) << 6;
    int lm = (lane >> 3) << 2, ln = (lane & 7) << 2;
    int am = tid & 127, akg = tid >> 7;
    int bn4 = tid & 31, bk0 = tid >> 5;

    ull acc[8][4];
#pragma unroll
    for (int r = 0; r < 8; r++)
#pragma unroll
        for (int s = 0; s < 4; s++) acc[r][s] = 0ULL;

    float4 aR[2], bR[2];
    const size_t arow = (size_t)(m0 + am) * K;

#define LDG_TILE(k0)                                                          \
    aR[0] = *(const float4*)&A[arow + (k0) + (akg << 2)];                     \
    aR[1] = *(const float4*)&A[arow + (k0) + ((akg + 2) << 2)];               \
    bR[0] = *(const float4*)&W[(size_t)((k0) + bk0) * G4 + n0 + (bn4 << 2)];  \
    bR[1] = *(const float4*)&W[(size_t)((k0) + bk0 + 8) * G4 + n0 + (bn4 << 2)];

#define STS_TILE(buf)                                                         \
    {                                                                         \
        float* Ad = As[buf]; float* Bd = Bs[buf];                             \
        Ad[((akg << 2) + 0) * 128 + am] = aR[0].x;                            \
        Ad[((akg << 2) + 1) * 128 + am] = aR[0].y;                            \
        Ad[((akg << 2) + 2) * 128 + am] = aR[0].z;                            \
        Ad[((akg << 2) + 3) * 128 + am] = aR[0].w;                            \
        Ad[(((akg + 2) << 2) + 0) * 128 + am] = aR[1].x;                      \
        Ad[(((akg + 2) << 2) + 1) * 128 + am] = aR[1].y;                      \
        Ad[(((akg + 2) << 2) + 2) * 128 + am] = aR[1].z;                      \
        Ad[(((akg + 2) << 2) + 3) * 128 + am] = aR[1].w;                      \
        *(float4*)&Bd[bk0 * 128 + (bn4 << 2)] = bR[0];                        \
        *(float4*)&Bd[(bk0 + 8) * 128 + (bn4 << 2)] = bR[1];                  \
    }

    LDG_TILE(0);
    STS_TILE(0);
    __syncthreads();

    int KT = K >> 4;
    for (int kt = 0; kt < KT; kt++) {
        int cur = kt & 1;
        if (kt + 1 < KT) { LDG_TILE((kt + 1) << 4); }
        const float* Ab = As[cur];
        const float* Bb = Bs[cur];
#pragma unroll
        for (int kk = 0; kk < 16; kk++) {
            float4 a0 = *(const float4*)&Ab[kk * 128 + wm + lm];
            float4 a1 = *(const float4*)&Ab[kk * 128 + wm + lm + 16];
            ulonglong2 b0 = *(const ulonglong2*)&Bb[kk * 128 + wn + ln];
            ulonglong2 b1 = *(const ulonglong2*)&Bb[kk * 128 + wn + ln + 32];
            ull ap[8];
            ap[0] = dup2(a0.x); ap[1] = dup2(a0.y); ap[2] = dup2(a0.z); ap[3] = dup2(a0.w);
            ap[4] = dup2(a1.x); ap[5] = dup2(a1.y); ap[6] = dup2(a1.z); ap[7] = dup2(a1.w);
#pragma unroll
            for (int r = 0; r < 8; r++) {
                fma2(acc[r][0], ap[r], b0.x);
                fma2(acc[r][1], ap[r], b0.y);
                fma2(acc[r][2], ap[r], b1.x);
                fma2(acc[r][3], ap[r], b1.y);
            }
        }
        if (kt + 1 < KT) {
            STS_TILE(cur ^ 1);
            __syncthreads();
        }
    }

    float4 bias0 = *(const float4*)&bias[n0 + wn + ln];
    float4 bias1 = *(const float4*)&bias[n0 + wn + ln + 32];
#pragma unroll
    for (int r = 0; r < 8; r++) {
        int mrow = m0 + wm + lm + (r < 4 ? r : 12 + r);
        float2 p0 = unpk(acc[r][0]), p1 = unpk(acc[r][1]);
        float2 p2 = unpk(acc[r][2]), p3 = unpk(acc[r][3]);
        float4 v0 = {p0.x + bias0.x, p0.y + bias0.y, p1.x + bias0.z, p1.y + bias0.w};
        float4 v1 = {p2.x + bias1.x, p2.y + bias1.y, p3.x + bias1.z, p3.y + bias1.w};
        size_t crow = (size_t)mrow * G4 + n0 + wn + ln;
        *(float4*)&C[crow] = v0;
        *(float4*)&C[crow + 32] = v1;
    }
#undef LDG_TILE
#undef STS_TILE
}

// ---------------- init: zero h buffers + barrier state ----------------
__global__ void init_state_kernel() {
    int i = blockIdx.x * blockDim.x + threadIdx.x;
    if (i < 2 * 2 * B * D) ((float*)g_h)[i] = 0.0f;
    if (i < 2) { g_bcount[i] = 0u; g_bgen[i] = 0u; }
}

// ---------------- persistent bidirectional LSTM scan (one layer) ----------------
// 128 CTAs (dir = blk>>6; 8 hidden units = 32 gate cols each), 128 threads.
// U staged ONCE in smem; c/h/prev_out live in registers; h crosses CTAs via
// global ping-pong + per-direction 64-CTA spin barrier.
#define SMEM_STEP ((64 * 512 + 32 * 512) * 4)

__device__ __forceinline__ void dir_barrier(int dir, unsigned target) {
    if (threadIdx.x == 0) {
        __threadfence();
        unsigned old = atomicAdd(&g_bcount[dir], 1u);
        if (old == 63u) {
            atomicExch(&g_bcount[dir], 0u);
            __threadfence();
            g_bgen[dir] = target;
        } else {
            while (g_bgen[dir] < target) __nanosleep(32);
            __threadfence();
        }
    }
    __syncthreads();
}

__global__ void __launch_bounds__(128) lstm_scan_kernel(
    const float* __restrict__ Uf, const float* __restrict__ Ub,
    float* dout, int out_is_y1)
{
    extern __shared__ float sm[];
    float* h_s = sm;               // 64 rows * 512, chunk-swizzled by (b>>3)
    float* u_s = sm + 64 * 512;    // 32 rows * 512, chunk-swizzled by (j>>2)

    int tid = threadIdx.x;
    int dir = blockIdx.x >> 6;
    int u0 = (blockIdx.x & 63) << 3;

    const float* U = dir ? Ub : Uf;
    const float* xz = dir ? g_xz_b : g_xz_f;
    float* outb = (out_is_y1 ? g_y1 : dout) + dir * D;

    // ---- stage U slice ONCE (32 cols x 512 k), swizzled ----
    for (int i = tid; i < 4096; i += 128) {
        int k = i >> 3, q = i & 7;
        int g = q >> 1, half = q & 1;
        int col = (g << 9) + u0 + (half << 2);
        float4 v = *(const float4*)&U[(size_t)k * G4 + col];
        int jb = (g << 3) + (half << 2);
        int chunk = k >> 2, klo = k & 3;
        const float* vp = (const float*)&v;
#pragma unroll
        for (int comp = 0; comp < 4; comp++) {
            int j = jb + comp;
            u_s[(j << 9) + (((chunk ^ ((j >> 2) & 7)) << 2) | klo)] = vp[comp];
        }
    }

    // persistent per-thread state: this thread owns (b = (tid+128j)>>3, u = tid&7)
    float c_reg[4]  = {0.f, 0.f, 0.f, 0.f};
    float h_reg[4]  = {0.f, 0.f, 0.f, 0.f};
    float po_reg[4] = {0.f, 0.f, 0.f, 0.f};

    int t = tid & 63, kg = tid >> 6;
    int tb = t >> 3, tc = t & 7;
    int b0 = tb << 3, c0 = tc << 2;
    int cbeg = kg << 6;
    const float* hbase = h_s + (b0 << 9);
    const float* ubase = u_s + (c0 << 9);
    int cb = u0 + (tid & 7);

    for (int s = 0; s < T; s++) {
        int ping = s & 1;
        int t_d = dir ? (T - 1 - s) : s;
        const float* h_in = g_h[ping] + dir * (B * D);
        float* h_out = g_h[ping ^ 1] + dir * (B * D);

        // ---- stage h [64,512] (L2-fresh via .cg; L1 may be stale) ----
        for (int i = tid; i < 64 * 128; i += 128) {
            int b = i >> 7, c = i & 127;
            float4 v = __ldcg((const float4*)&h_in[(b << 9) + (c << 2)]);
            *(float4*)&h_s[(b << 9) + ((c ^ ((b >> 3) & 7)) << 2)] = v;
        }

        // ---- prefetch xz + mask for this step (consumed after compute) ----
        float xzr[4][4];
        unsigned char mr[4];
#pragma unroll
        for (int j = 0; j < 4; j++) {
            int b = (tid + (j << 7)) >> 3;
            int row = b * T + t_d;
            size_t xr = (size_t)row * G4;
            xzr[j][0] = xz[xr + cb];
            xzr[j][1] = xz[xr + 512 + cb];
            xzr[j][2] = xz[xr + 1024 + cb];
            xzr[j][3] = xz[xr + 1536 + cb];
            mr[j] = g_mask[row];
        }
        __syncthreads();

        // ---- z[64][32] = h @ U_slice ----
        ull acc[8][4];
#pragma unroll
        for (int r = 0; r < 8; r++)
#pragma unroll
            for (int ss = 0; ss < 4; ss++) acc[r][ss] = 0ULL;

#pragma unroll 2
        for (int ci = 0; ci < 64; ci++) {
            int c = cbeg + ci;
            int ph = (c ^ tb) << 2;
            int pu = (c ^ tc) << 2;
            ulonglong2 hv[8], uv[4];
#pragma unroll
            for (int r = 0; r < 8; r++) hv[r] = *(const ulonglong2*)&hbase[(r << 9) + ph];
#pragma unroll
            for (int ss = 0; ss < 4; ss++) uv[ss] = *(const ulonglong2*)&ubase[(ss << 9) + pu];
#pragma unroll
            for (int r = 0; r < 8; r++)
#pragma unroll
                for (int ss = 0; ss < 4; ss++) {
                    fma2(acc[r][ss], hv[r].x, uv[ss].x);
                    fma2(acc[r][ss], hv[r].y, uv[ss].y);
                }
        }
        __syncthreads();

        // ---- combine partials into z_s[64][33] (aliases h_s region) ----
        float* z_s = sm;
        if (kg == 0) {
#pragma unroll
            for (int r = 0; r < 8; r++)
#pragma unroll
                for (int ss = 0; ss < 4; ss++) {
                    float2 f = unpk(acc[r][ss]);
                    z_s[(b0 + r) * 33 + c0 + ss] = f.x + f.y;
                }
        }
        __syncthreads();
        if (kg == 1) {
#pragma unroll
            for (int r = 0; r < 8; r++)
#pragma unroll
                for (int ss = 0; ss < 4; ss++) {
                    float2 f = unpk(acc[r][ss]);
                    z_s[(b0 + r) * 33 + c0 + ss] += f.x + f.y;
                }
        }
        __syncthreads();

        // ---- gates + state update (register-resident c/h/prev) ----
        int u = tid & 7;
#pragma unroll
        for (int j = 0; j < 4; j++) {
            int b = (tid + (j << 7)) >> 3;
            int row = b * T + t_d;
            float zi = z_s[b * 33 + u]      + xzr[j][0];
            float zf = z_s[b * 33 + 8 + u]  + xzr[j][1];
            float zg = z_s[b * 33 + 16 + u] + xzr[j][2];
            float zo = z_s[b * 33 + 24 + u] + xzr[j][3];
            float iv = 1.0f / (1.0f + expf(-zi));
            float fv = 1.0f / (1.0f + expf(-zf));
            float gv = tanhf(zg);
            float ov = 1.0f / (1.0f + expf(-zo));
            float c_new = fv * c_reg[j] + iv * gv;
            float h_new = ov * tanhf(c_new);
            bool m = mr[j] != 0;
            c_reg[j]  = m ? c_new : c_reg[j];
            h_reg[j]  = m ? h_new : h_reg[j];
            po_reg[j] = m ? h_new : po_reg[j];
            h_out[b * D + cb] = h_reg[j];
            outb[(size_t)row * 1024 + cb] = po_reg[j];
        }

        if (s + 1 < T) dir_barrier(dir, (unsigned)(s + 1));
    }

    // final cell state for finalize (only layer 2 is consumed; write always)
#pragma unroll
    for (int j = 0; j < 4; j++) {
        int b = (tid + (j << 7)) >> 3;
        g_c[dir * (B * D) + b * D + cb] = c_reg[j];
    }
}

// ---------------- final hidden/cell concat ----------------
__global__ void finalize_kernel(float* dout, int out_size) {
    int i = blockIdx.x * blockDim.x + threadIdx.x;
    if (i >= B * 2 * D) return;
    size_t hoff = (size_t)B * T * 1024;
    if ((size_t)out_size < hoff + 2 * (size_t)(B * 2 * D)) return;
    int b = i >> 10, j = i & 1023;
    int dir = j >> 9, u = j & 511;
    int sidx = dir * (B * D) + b * D + u;
    dout[hoff + i] = g_h[0][sidx];   // 256 steps => final ping = 0
    dout[hoff + B * 2 * D + i] = g_c[sidx];
}

// ---------------- host orchestration ----------------
extern "C" void kernel_launch(void* const* d_in, const int* in_sizes, int n_in,
                              void* d_out, int out_size) {
    const float* X   = (const float*)d_in[0];
    const float* Wf1 = (const float*)d_in[1];
    const float* Uf1 = (const float*)d_in[2];
    const float* bf1 = (const float*)d_in[3];
    const float* Wb1 = (const float*)d_in[4];
    const float* Ub1 = (const float*)d_in[5];
    const float* bb1 = (const float*)d_in[6];
    const float* Wf2 = (const float*)d_in[7];
    const float* Uf2 = (const float*)d_in[8];
    const float* bf2 = (const float*)d_in[9];
    const float* Wb2 = (const float*)d_in[10];
    const float* Ub2 = (const float*)d_in[11];
    const float* bb2 = (const float*)d_in[12];
    float* out = (float*)d_out;

    cudaFuncSetAttribute(lstm_scan_kernel,
                         cudaFuncAttributeMaxDynamicSharedMemorySize, SMEM_STEP);

    mask_kernel<<<M_ROWS / 4, 128>>>(X);

    dim3 ggrid(G4 / 128, M_ROWS / 128);

    // ---- layer 1 ----
    gemm_bias_kernel<<<ggrid, 256>>>(X, 0, Wf1, bf1, 0, 512);
    gemm_bias_kernel<<<ggrid, 256>>>(X, 0, Wb1, bb1, 1, 512);
    init_state_kernel<<<512, 256>>>();
    lstm_scan_kernel<<<128, 128, SMEM_STEP>>>(Uf1, Ub1, out, 1);

    // ---- layer 2 ----
    gemm_bias_kernel<<<ggrid, 256>>>(nullptr, 1, Wf2, bf2, 0, 1024);
    gemm_bias_kernel<<<ggrid, 256>>>(nullptr, 1, Wb2, bb2, 1, 1024);
    init_state_kernel<<<512, 256>>>();
    lstm_scan_kernel<<<128, 128, SMEM_STEP>>>(Uf2, Ub2, out, 0);

    finalize_kernel<<<256, 256>>>(out, out_size);
}